// round 15
// baseline (speedup 1.0000x reference)
#include <cuda_runtime.h>
#include <cuda_fp16.h>
#include <cstdint>

// ---------------------------------------------------------------------------
// TriXLinear (sm_103 baseline PTX; tensor path = mma.sync m16n8k16 f16).
//   out = (x @ sign(W)^T) * scales * gate_mask
// x -> fp16 (norm rel err ~2.1e-4), W -> +-1 fp16 (exact). Gated-row GEMM.
// R15 = R13 + two proven-machinery upgrades:
//  - compact_parts: 16 blocks x 256 rows, emits BOTH gated and ungated row
//    lists (same warp-aggregated code shape, passing since R10).
//  - zero-ungated fused into GEMM prologue via the SAME per-part prefix walk
//    used for srow (ungated prefix upre[p] = 256p - pre[p]); issued after the
//    TMA prologue where GEMM DRAM is ~idle. Prep loses its zero partition.
// GEMM core: R6/R13 (warp 64x64, block 128x128, 3-stage bulk-TMA, 2 CTAs/SM).
// ---------------------------------------------------------------------------

#define MDIM 4096
#define NDIM 4096
#define KDIM 4096
#define NPART 16                        // compaction parts (256 rows each)

#define NKT 64                          // K stages (64 fp16 = 128B rows)
#define STAGES 3
#define STAGE_BYTES 32768               // A 16K + B 16K
#define SMEM_SC   64                    // scales (512B)            64..576
#define SMEM_SROW 576                   // gated row ids (512B)    576..1088
#define SMEM_PRE  1088                  // part prefix (17 ints)  1088..1156
#define SMEM_UROW 1216                  // ungated row ids (512B) 1216..1728
#define SMEM_ST   2048
#define SMEM_TOTAL (SMEM_ST + STAGES * STAGE_BYTES)   // 100352 -> 2 CTAs/SM
// mbarriers: full[s] at sb+8s, empty[s] at sb+24+8s  (s = 0..2)

// merged-prep partition
#define GATHER_BLKS 2048                // 32 mblk x 4 t x 16 kg
#define SIGNW_BLKS  8192
#define PREP_BLKS   (GATHER_BLKS + SIGNW_BLKS)

// ------------------------------- scratch -----------------------------------
__device__ __align__(1024) unsigned char g_Wt[(size_t)32 * 1024 * 1024];
__device__ __align__(1024) unsigned char g_At[(size_t)128 * 1024 * 1024];
__device__ int g_cntp[4][NPART];              // per-tile per-part gated counts
__device__ int g_rows_part[4][NPART][256];    // per-part gated row ids
__device__ int g_urows_part[4][NPART][256];   // per-part ungated row ids

// ------------------------------ PTX helpers --------------------------------
__device__ __forceinline__ uint32_t smem_u32(const void* p) {
    uint32_t a;
    asm("{ .reg .u64 t; cvta.to.shared.u64 t, %1; cvt.u32.u64 %0, t; }"
        : "=r"(a) : "l"(p));
    return a;
}
__device__ __forceinline__ uint32_t elect_one() {
    uint32_t p;
    asm volatile("{ .reg .pred p; elect.sync _|p, 0xFFFFFFFF; selp.b32 %0,1,0,p; }"
                 : "=r"(p));
    return p;
}
__device__ __forceinline__ void mbar_init(uint32_t mb, uint32_t cnt) {
    asm volatile("mbarrier.init.shared.b64 [%0], %1;" :: "r"(mb), "r"(cnt) : "memory");
}
__device__ __forceinline__ void mbar_expect_tx(uint32_t mb, uint32_t bytes) {
    asm volatile("mbarrier.arrive.expect_tx.shared.b64 _, [%0], %1;"
                 :: "r"(mb), "r"(bytes) : "memory");
}
__device__ __forceinline__ void mbar_arrive(uint32_t mb) {
    asm volatile("mbarrier.arrive.shared.b64 _, [%0];" :: "r"(mb) : "memory");
}
__device__ __forceinline__ void mbar_wait(uint32_t mb, uint32_t parity) {
    asm volatile(
        "{\n\t.reg .pred P;\n\t"
        "WL_%=:\n\t"
        "mbarrier.try_wait.parity.acquire.cta.shared::cta.b64 P, [%0], %1, 0x989680;\n\t"
        "@P bra.uni WD_%=;\n\t"
        "bra.uni WL_%=;\n\t"
        "WD_%=:\n\t}"
        :: "r"(mb), "r"(parity) : "memory");
}
__device__ __forceinline__ void bulk_g2s(uint32_t dst, const void* src,
                                         uint32_t bytes, uint32_t mb) {
    asm volatile(
        "cp.async.bulk.shared::cta.global.mbarrier::complete_tx::bytes "
        "[%0], [%1], %2, [%3];"
        :: "r"(dst), "l"(src), "r"(bytes), "r"(mb) : "memory");
}
__device__ __forceinline__ void ldm_x4(uint32_t* r, uint32_t addr) {
    asm volatile("ldmatrix.sync.aligned.m8n8.x4.shared.b16 {%0,%1,%2,%3}, [%4];"
                 : "=r"(r[0]), "=r"(r[1]), "=r"(r[2]), "=r"(r[3]) : "r"(addr));
}
__device__ __forceinline__ void hmma(float* c, const uint32_t* a,
                                     uint32_t b0, uint32_t b1) {
    asm volatile(
        "mma.sync.aligned.m16n8k16.row.col.f32.f16.f16.f32 "
        "{%0,%1,%2,%3}, {%4,%5,%6,%7}, {%8,%9}, {%0,%1,%2,%3};"
        : "+f"(c[0]), "+f"(c[1]), "+f"(c[2]), "+f"(c[3])
        : "r"(a[0]), "r"(a[1]), "r"(a[2]), "r"(a[3]), "r"(b0), "r"(b1));
}

// --------------------------- compact (16 blocks) ----------------------------
// part p handles rows [p*256, (p+1)*256); emits gated AND ungated lists via
// warp-aggregated atomics on per-part smem counters (order irrelevant).
__global__ void compact_parts(const int* __restrict__ gate) {
    const int p = blockIdx.x;
    __shared__ int scnt[4], sucnt[4];
    int tid = threadIdx.x;
    if (tid < 4) { scnt[tid] = 0; sucnt[tid] = 0; }
    __syncthreads();
    int lane = tid & 31;
    int r = p * 256 + tid;
#pragma unroll
    for (int t = 0; t < 4; t++) {
        bool pred = (gate[r * 4 + t] != 0);
        unsigned mask = __ballot_sync(0xFFFFFFFFu, pred);
        int cnt = __popc(mask);
        int base = 0;
        if (lane == 0 && cnt) base = atomicAdd(&scnt[t], cnt);
        base = __shfl_sync(0xFFFFFFFFu, base, 0);
        unsigned umask = ~mask;
        int ucnt = 32 - cnt;
        int ubase = 0;
        if (lane == 0 && ucnt) ubase = atomicAdd(&sucnt[t], ucnt);
        ubase = __shfl_sync(0xFFFFFFFFu, ubase, 0);
        if (pred) {
            int rank = __popc(mask & ((1u << lane) - 1u));
            g_rows_part[t][p][base + rank] = r;
        } else {
            int urank = __popc(umask & ((1u << lane) - 1u));
            g_urows_part[t][p][ubase + urank] = r;
        }
    }
    __syncthreads();
    if (tid < 4) g_cntp[tid][p] = scnt[tid];
}

// ------------------------------ merged prep ---------------------------------
// blockIdx.x partition:
//   [0, 2048)     gather+quant: gated f32 x rows -> fp16 swizzled A tiles
//   [2048, ...)   sign_w -> fp16 swizzled tiles
__global__ __launch_bounds__(256) void prep_merged(
    const float* __restrict__ x,
    const float* __restrict__ w) {
    const int b = blockIdx.x;
    const int tid = threadIdx.x;

    if (b < GATHER_BLKS) {
        int mblk = b & 31, t = (b >> 5) & 3, kg = b >> 7;
        __shared__ int pre[NPART + 1];
        __shared__ int srow[128];
        if (tid == 0) {
            int acc = 0;
#pragma unroll
            for (int p = 0; p < NPART; p++) { pre[p] = acc; acc += g_cntp[t][p]; }
            pre[NPART] = acc;
        }
        __syncthreads();
        const int cnt = pre[NPART];
        if (mblk * 128 >= cnt || cnt == 0) return;
        if (tid < 128) {
            int gidx = mblk * 128 + tid;
            if (gidx >= cnt) gidx = cnt - 1;
            int p = 0;
#pragma unroll
            for (int q = 1; q < NPART; q++) p += (gidx >= pre[q]) ? 1 : 0;
            srow[tid] = g_rows_part[t][p][gidx - pre[p]];
        }
        __syncthreads();
        size_t bbase = ((size_t)(t * 32 + mblk)) << 20;
        int r = tid >> 3, c = tid & 7;        // 32 rows x 8 chunks / pass
#pragma unroll
        for (int kb = 0; kb < 4; kb++) {
            int kblk = kg * 4 + kb;
            size_t db = bbase + ((size_t)kblk << 14);
#pragma unroll
            for (int rp = 0; rp < 4; rp++) {
                int rr = r + rp * 32;
                const float4* src = reinterpret_cast<const float4*>(
                    x + (size_t)srow[rr] * KDIM + kblk * 64 + c * 8);
                float4 v0 = src[0], v1 = src[1];
                __half h[8];
                h[0] = __float2half_rn(v0.x); h[1] = __float2half_rn(v0.y);
                h[2] = __float2half_rn(v0.z); h[3] = __float2half_rn(v0.w);
                h[4] = __float2half_rn(v1.x); h[5] = __float2half_rn(v1.y);
                h[6] = __float2half_rn(v1.z); h[7] = __float2half_rn(v1.w);
                size_t dd = db + (size_t)rr * 128 + ((size_t)(c ^ (rr & 7)) << 4);
                *reinterpret_cast<uint4*>(g_At + dd) = *reinterpret_cast<uint4*>(h);
            }
        }
    } else {
        // ---- sign(W) -> fp16 swizzled tiles ----
        size_t idx = (size_t)(b - GATHER_BLKS) * 256 + tid;   // *8 elems
        int row = (int)(idx >> 9);
        int k0  = ((int)idx & 511) * 8;
        const float4* pp = reinterpret_cast<const float4*>(w + (size_t)row * KDIM + k0);
        float4 v0 = pp[0], v1 = pp[1];
        float f[8] = {v0.x, v0.y, v0.z, v0.w, v1.x, v1.y, v1.z, v1.w};
        __half s[8];
#pragma unroll
        for (int j = 0; j < 8; j++)
            s[j] = __float2half_rn((f[j] > 0.f) ? 1.f : ((f[j] < 0.f) ? -1.f : 0.f));
        int nb = row >> 7, r = row & 127, kblk = k0 >> 6;
        int c = (k0 & 63) >> 3;
        size_t off = (((size_t)(nb * 64 + kblk)) << 14) +
                     (size_t)r * 128 + ((size_t)(c ^ (r & 7)) << 4);
        *reinterpret_cast<uint4*>(g_Wt + off) = *reinterpret_cast<uint4*>(s);
    }
}

// ------------------------------ GEMM kernel ---------------------------------
// grid (8 nblk, 32 mblk, 4 t), 128 threads, warp grid 2(M) x 2(N), warp 64x64.
// Prologue: prefix walk -> srow (gated) + urow (ungated, upre = 256p - pre);
// fused zero of ungated rows after TMA prologue; R6 mainloop.

__global__ __launch_bounds__(128, 2) void trix_hmma(
    const float* __restrict__ scales,
    float* __restrict__ out) {
    const int t = blockIdx.z, mblk = blockIdx.y, nblk = blockIdx.x;

    extern __shared__ char smem[];
    const uint32_t sb = smem_u32(smem);
    const int tid = threadIdx.x;
    const int warp = tid >> 5, lane = tid & 31;
    const int wm = warp >> 1, wn = warp & 1;
    const int n0 = t * 1024 + nblk * 128;
    const int nb = t * 8 + nblk;

    int* pre  = reinterpret_cast<int*>(smem + SMEM_PRE);
    int* srow = reinterpret_cast<int*>(smem + SMEM_SROW);
    int* urow = reinterpret_cast<int*>(smem + SMEM_UROW);

    reinterpret_cast<float*>(smem + SMEM_SC)[tid] = scales[n0 + tid];
    if (tid == 0) {
        int acc = 0;
#pragma unroll
        for (int p = 0; p < NPART; p++) { pre[p] = acc; acc += g_cntp[t][p]; }
        pre[NPART] = acc;
#pragma unroll
        for (int s = 0; s < STAGES; s++) {
            mbar_init(sb + 8u * s, 1);        // full: TMA tx
            mbar_init(sb + 24u + 8u * s, 4);  // empty: 4 warp arrivals
        }
    }
    __syncthreads();

    const int cnt  = pre[NPART];
    const int cntu = MDIM - cnt;
    const bool active  = (mblk * 128 < cnt);
    const bool zactive = (mblk * 128 < cntu);
    if (!active && !zactive) return;

    if (active) {   // srow window via gated prefix walk (R13 machinery)
        int gidx = mblk * 128 + tid;
        if (gidx >= cnt) gidx = cnt - 1;
        int p = 0;
#pragma unroll
        for (int q = 1; q < NPART; q++) p += (gidx >= pre[q]) ? 1 : 0;
        srow[tid] = g_rows_part[t][p][gidx - pre[p]];
    }
    if (zactive) {  // urow window via ungated prefix: upre[p] = 256p - pre[p]
        int gidx = mblk * 128 + tid;
        if (gidx >= cntu) gidx = cntu - 1;    // duplicate zeroing is idempotent
        int p = 0;
#pragma unroll
        for (int q = 1; q < NPART; q++) p += (gidx >= 256 * q - pre[q]) ? 1 : 0;
        urow[tid] = g_urows_part[t][p][gidx - (256 * p - pre[p])];
    }

    const unsigned char* aSrc = g_At + (((size_t)(t * 32 + mblk)) << 20);
    const unsigned char* bSrc = g_Wt + ((size_t)nb << 20);

    auto fill = [&](int s, int kt) {
        uint32_t mb = sb + 8u * s;
        uint32_t st = sb + SMEM_ST + s * STAGE_BYTES;
        mbar_expect_tx(mb, STAGE_BYTES);
        bulk_g2s(st,         aSrc + ((size_t)kt << 14), 16384, mb);
        bulk_g2s(st + 16384, bSrc + ((size_t)kt << 14), 16384, mb);
    };
    const bool prod = (warp == 0) && elect_one();
    if (active && prod) {
#pragma unroll
        for (int s = 0; s < STAGES; s++) fill(s, s);
    }
    __syncthreads();   // srow/urow ready; TMA already in flight

    // fused zero of ungated rows (overlaps TMA prologue; GEMM DRAM is idle)
    if (zactive) {
        int lim = cntu - mblk * 128;
        if (lim > 128) lim = 128;
        float4 z = {0.f, 0.f, 0.f, 0.f};
#pragma unroll 4
        for (int jr = 0; jr < 32; jr++) {
            int j = jr * 4 + warp;
            if (j < lim) {
                int row = urow[j];
                reinterpret_cast<float4*>(out + (size_t)row * NDIM + n0)[lane] = z;
            }
        }
    }
    if (!active) return;

    // ldmatrix addressing
    int aR[4], bR[4];
#pragma unroll
    for (int ms = 0; ms < 4; ms++) aR[ms] = wm * 64 + ms * 16 + (lane & 15);
    const int aCadd = lane >> 4;
#pragma unroll
    for (int nq = 0; nq < 4; nq++)
        bR[nq] = wn * 64 + nq * 16 + (lane & 7) + ((lane >> 4) << 3);
    const int bCadd = (lane >> 3) & 1;

    float d[4][8][4];
#pragma unroll
    for (int a = 0; a < 4; a++)
#pragma unroll
        for (int b = 0; b < 8; b++)
#pragma unroll
            for (int c = 0; c < 4; c++) d[a][b][c] = 0.f;

    for (int kt = 0; kt < NKT; kt++) {
        const int s = kt % 3;
        const uint32_t ph = (uint32_t)((kt / 3) & 1);
        mbar_wait(sb + 8u * s, ph);                       // data ready
        const uint32_t st = sb + SMEM_ST + s * STAGE_BYTES;
#pragma unroll
        for (int ks = 0; ks < 4; ks++) {
            uint32_t a[4][4], bf[4][4];
#pragma unroll
            for (int ms = 0; ms < 4; ms++) {
                uint32_t off = aR[ms] * 128 +
                               (((ks * 2 + aCadd) ^ (aR[ms] & 7)) << 4);
                ldm_x4(a[ms], st + off);
            }
#pragma unroll
            for (int nq = 0; nq < 4; nq++) {
                uint32_t off = bR[nq] * 128 +
                               (((ks * 2 + bCadd) ^ (bR[nq] & 7)) << 4);
                ldm_x4(bf[nq], st + 16384 + off);
            }
#pragma unroll
            for (int ms = 0; ms < 4; ms++)
#pragma unroll
                for (int nq = 0; nq < 4; nq++) {
                    hmma(d[ms][nq * 2],     a[ms], bf[nq][0], bf[nq][1]);
                    hmma(d[ms][nq * 2 + 1], a[ms], bf[nq][2], bf[nq][3]);
                }
        }
        if (elect_one()) mbar_arrive(sb + 24u + 8u * s);  // warp consumed
        if (prod && kt + STAGES < NKT) {
            mbar_wait(sb + 24u + 8u * s, ph);             // all 4 consumed
            fill(s, kt + STAGES);
        }
    }

    // epilogue: out = acc * scales[col] for gated rows (srow in smem)
    const float* sSc = reinterpret_cast<const float*>(smem + SMEM_SC);
#pragma unroll
    for (int ms = 0; ms < 4; ms++) {
#pragma unroll
        for (int half = 0; half < 2; half++) {
            int j = wm * 64 + ms * 16 + (lane >> 2) + half * 8;
            if (mblk * 128 + j >= cnt) continue;
            int row = srow[j];
            float* orow = out + (size_t)row * NDIM + n0;
#pragma unroll
            for (int ns = 0; ns < 8; ns++) {
                int col = wn * 64 + ns * 8 + (lane & 3) * 2;
                float2 v;
                v.x = d[ms][ns][half * 2]     * sSc[col];
                v.y = d[ms][ns][half * 2 + 1] * sSc[col + 1];
                *reinterpret_cast<float2*>(orow + col) = v;
            }
        }
    }
}

// ------------------------------ launch --------------------------------------

extern "C" void kernel_launch(void* const* d_in, const int* in_sizes, int n_in,
                              void* d_out, int out_size) {
    const float* x      = (const float*)d_in[0];
    const int*   gate   = (const int*)d_in[1];
    const float* weight = (const float*)d_in[2];
    const float* scales = (const float*)d_in[3];
    float* out = (float*)d_out;

    cudaFuncSetAttribute(trix_hmma,
                         cudaFuncAttributeMaxDynamicSharedMemorySize, SMEM_TOTAL);

    compact_parts<<<NPART, 256>>>(gate);
    prep_merged<<<PREP_BLKS, 256>>>(x, weight);
    trix_hmma<<<dim3(8, 32, 4), 128, SMEM_TOTAL>>>(scales, out);
}

// round 16
// speedup vs baseline: 1.3943x; 1.3943x over previous
#include <cuda_runtime.h>
#include <cuda_fp16.h>
#include <cstdint>

// ---------------------------------------------------------------------------
// TriXLinear (sm_103 baseline PTX; tensor path = mma.sync m16n8k16 f16).
//   out = (x @ sign(W)^T) * scales * gate_mask
// x -> fp16 (norm rel err ~2.1e-4), W -> +-1 fp16 (exact). Gated-row GEMM.
// R16 = R13 verbatim (measured best: 212.6us). Final consolidation:
//  - compact: 8 parallel per-part blocks
//  - prep: ONE merged kernel = gather+quant | sign_w | zero-ungated
//  - GEMM: warp 64x64, block 128x128, 3-stage bulk-TMA mbarrier pipeline,
//    producer-only empty wait, 2 CTAs/SM; srow prefix-walk prologue.
// ---------------------------------------------------------------------------

#define MDIM 4096
#define NDIM 4096
#define KDIM 4096

#define NKT 64                          // K stages (64 fp16 = 128B rows)
#define STAGES 3
#define STAGE_BYTES 32768               // A 16K + B 16K
#define SMEM_SC   64                    // scales (512B)
#define SMEM_SROW 576                   // gathered row ids (512B)
#define SMEM_PRE  1088                  // part prefix (9 ints)
#define SMEM_ST   2048
#define SMEM_TOTAL (SMEM_ST + STAGES * STAGE_BYTES)   // 100352 -> 2 CTAs/SM
// mbarriers: full[s] at sb+8s, empty[s] at sb+24+8s  (s = 0..2)

// merged-prep partition
#define GATHER_BLKS 2048                // 32 mblk x 4 t x 16 kg
#define SIGNW_BLKS  8192
#define ZERO_BLKS   16384
#define PREP_BLKS   (GATHER_BLKS + SIGNW_BLKS + ZERO_BLKS)

// ------------------------------- scratch -----------------------------------
__device__ __align__(1024) unsigned char g_Wt[(size_t)32 * 1024 * 1024];
__device__ __align__(1024) unsigned char g_At[(size_t)128 * 1024 * 1024];
__device__ int g_cntp[4][8];            // per-tile per-part gated-row counts
__device__ int g_rows_part[4][8][512];  // per-part compacted row ids

// ------------------------------ PTX helpers --------------------------------
__device__ __forceinline__ uint32_t smem_u32(const void* p) {
    uint32_t a;
    asm("{ .reg .u64 t; cvta.to.shared.u64 t, %1; cvt.u32.u64 %0, t; }"
        : "=r"(a) : "l"(p));
    return a;
}
__device__ __forceinline__ uint32_t elect_one() {
    uint32_t p;
    asm volatile("{ .reg .pred p; elect.sync _|p, 0xFFFFFFFF; selp.b32 %0,1,0,p; }"
                 : "=r"(p));
    return p;
}
__device__ __forceinline__ void mbar_init(uint32_t mb, uint32_t cnt) {
    asm volatile("mbarrier.init.shared.b64 [%0], %1;" :: "r"(mb), "r"(cnt) : "memory");
}
__device__ __forceinline__ void mbar_expect_tx(uint32_t mb, uint32_t bytes) {
    asm volatile("mbarrier.arrive.expect_tx.shared.b64 _, [%0], %1;"
                 :: "r"(mb), "r"(bytes) : "memory");
}
__device__ __forceinline__ void mbar_arrive(uint32_t mb) {
    asm volatile("mbarrier.arrive.shared.b64 _, [%0];" :: "r"(mb) : "memory");
}
__device__ __forceinline__ void mbar_wait(uint32_t mb, uint32_t parity) {
    asm volatile(
        "{\n\t.reg .pred P;\n\t"
        "WL_%=:\n\t"
        "mbarrier.try_wait.parity.acquire.cta.shared::cta.b64 P, [%0], %1, 0x989680;\n\t"
        "@P bra.uni WD_%=;\n\t"
        "bra.uni WL_%=;\n\t"
        "WD_%=:\n\t}"
        :: "r"(mb), "r"(parity) : "memory");
}
__device__ __forceinline__ void bulk_g2s(uint32_t dst, const void* src,
                                         uint32_t bytes, uint32_t mb) {
    asm volatile(
        "cp.async.bulk.shared::cta.global.mbarrier::complete_tx::bytes "
        "[%0], [%1], %2, [%3];"
        :: "r"(dst), "l"(src), "r"(bytes), "r"(mb) : "memory");
}
__device__ __forceinline__ void ldm_x4(uint32_t* r, uint32_t addr) {
    asm volatile("ldmatrix.sync.aligned.m8n8.x4.shared.b16 {%0,%1,%2,%3}, [%4];"
                 : "=r"(r[0]), "=r"(r[1]), "=r"(r[2]), "=r"(r[3]) : "r"(addr));
}
__device__ __forceinline__ void hmma(float* c, const uint32_t* a,
                                     uint32_t b0, uint32_t b1) {
    asm volatile(
        "mma.sync.aligned.m16n8k16.row.col.f32.f16.f16.f32 "
        "{%0,%1,%2,%3}, {%4,%5,%6,%7}, {%8,%9}, {%0,%1,%2,%3};"
        : "+f"(c[0]), "+f"(c[1]), "+f"(c[2]), "+f"(c[3])
        : "r"(a[0]), "r"(a[1]), "r"(a[2]), "r"(a[3]), "r"(b0), "r"(b1));
}

// --------------------------- compact (8 blocks) -----------------------------
// part p handles rows [p*512, (p+1)*512); per-part counters, no cross-block
// atomics, so no zeroing dependency and no serialization.
__global__ void compact_parts(const int* __restrict__ gate) {
    const int p = blockIdx.x;
    __shared__ int scnt[4];
    int tid = threadIdx.x;
    if (tid < 4) scnt[tid] = 0;
    __syncthreads();
    int lane = tid & 31;
#pragma unroll
    for (int h = 0; h < 2; h++) {
        int r = p * 512 + h * 256 + tid;
#pragma unroll
        for (int t = 0; t < 4; t++) {
            bool pred = (gate[r * 4 + t] != 0);
            unsigned mask = __ballot_sync(0xFFFFFFFFu, pred);
            int cnt = __popc(mask);
            int base = 0;
            if (lane == 0 && cnt) base = atomicAdd(&scnt[t], cnt);
            base = __shfl_sync(0xFFFFFFFFu, base, 0);
            if (pred) {
                int rank = __popc(mask & ((1u << lane) - 1u));
                g_rows_part[t][p][base + rank] = r;
            }
        }
    }
    __syncthreads();
    if (tid < 4) g_cntp[tid][p] = scnt[tid];
}

// ------------------------------ merged prep ---------------------------------
// blockIdx.x partition:
//   [0, 2048)     gather+quant: gated f32 x rows -> fp16 swizzled A tiles
//   [2048, 10240) sign_w -> fp16 swizzled tiles
//   [10240, ...)  zero ungated (row, tile) out blocks
__global__ __launch_bounds__(256) void prep_merged(
    const float* __restrict__ x,
    const float* __restrict__ w,
    const int* __restrict__ gate,
    float* __restrict__ out) {
    const int b = blockIdx.x;
    const int tid = threadIdx.x;

    if (b < GATHER_BLKS) {
        int mblk = b & 31, t = (b >> 5) & 3, kg = b >> 7;
        __shared__ int pre[9];
        __shared__ int srow[128];
        if (tid == 0) {
            int acc = 0;
#pragma unroll
            for (int p = 0; p < 8; p++) { pre[p] = acc; acc += g_cntp[t][p]; }
            pre[8] = acc;
        }
        __syncthreads();
        const int cnt = pre[8];
        if (mblk * 128 >= cnt || cnt == 0) return;
        if (tid < 128) {
            int gidx = mblk * 128 + tid;
            if (gidx >= cnt) gidx = cnt - 1;
            int p = 0;
#pragma unroll
            for (int q = 1; q < 8; q++) p += (gidx >= pre[q]) ? 1 : 0;
            srow[tid] = g_rows_part[t][p][gidx - pre[p]];
        }
        __syncthreads();
        size_t base = ((size_t)(t * 32 + mblk)) << 20;
        int r = tid >> 3, c = tid & 7;        // 32 rows x 8 chunks / pass
#pragma unroll
        for (int kb = 0; kb < 4; kb++) {
            int kblk = kg * 4 + kb;
            size_t db = base + ((size_t)kblk << 14);
#pragma unroll
            for (int rp = 0; rp < 4; rp++) {
                int rr = r + rp * 32;
                const float4* src = reinterpret_cast<const float4*>(
                    x + (size_t)srow[rr] * KDIM + kblk * 64 + c * 8);
                float4 v0 = src[0], v1 = src[1];
                __half h[8];
                h[0] = __float2half_rn(v0.x); h[1] = __float2half_rn(v0.y);
                h[2] = __float2half_rn(v0.z); h[3] = __float2half_rn(v0.w);
                h[4] = __float2half_rn(v1.x); h[5] = __float2half_rn(v1.y);
                h[6] = __float2half_rn(v1.z); h[7] = __float2half_rn(v1.w);
                size_t dd = db + (size_t)rr * 128 + ((size_t)(c ^ (rr & 7)) << 4);
                *reinterpret_cast<uint4*>(g_At + dd) = *reinterpret_cast<uint4*>(h);
            }
        }
    } else if (b < GATHER_BLKS + SIGNW_BLKS) {
        size_t idx = (size_t)(b - GATHER_BLKS) * 256 + tid;   // *8 elems
        int row = (int)(idx >> 9);
        int k0  = ((int)idx & 511) * 8;
        const float4* pp = reinterpret_cast<const float4*>(w + (size_t)row * KDIM + k0);
        float4 v0 = pp[0], v1 = pp[1];
        float f[8] = {v0.x, v0.y, v0.z, v0.w, v1.x, v1.y, v1.z, v1.w};
        __half s[8];
#pragma unroll
        for (int j = 0; j < 8; j++)
            s[j] = __float2half_rn((f[j] > 0.f) ? 1.f : ((f[j] < 0.f) ? -1.f : 0.f));
        int nb = row >> 7, r = row & 127, kblk = k0 >> 6;
        int c = (k0 & 63) >> 3;
        size_t off = (((size_t)(nb * 64 + kblk)) << 14) +
                     (size_t)r * 128 + ((size_t)(c ^ (r & 7)) << 4);
        *reinterpret_cast<uint4*>(g_Wt + off) = *reinterpret_cast<uint4*>(s);
    } else {
        int bid = b - (GATHER_BLKS + SIGNW_BLKS);   // 16384
        int r = bid >> 2, t = bid & 3;
        if (gate[r * 4 + t] != 0) return;
        float4 z = {0.f, 0.f, 0.f, 0.f};
        reinterpret_cast<float4*>(out + (size_t)r * NDIM + t * 1024)[tid] = z;
    }
}

// ------------------------------ GEMM kernel ---------------------------------
// grid (8 nblk, 32 mblk, 4 t), 128 threads, warp grid 2(M) x 2(N), warp 64x64.
// R6 mainloop; prologue rebuilds srow from per-part counters for the epilogue.

__global__ __launch_bounds__(128, 2) void trix_hmma(
    const float* __restrict__ scales,
    float* __restrict__ out) {
    const int t = blockIdx.z, mblk = blockIdx.y, nblk = blockIdx.x;

    extern __shared__ char smem[];
    const uint32_t sb = smem_u32(smem);
    const int tid = threadIdx.x;
    const int warp = tid >> 5, lane = tid & 31;
    const int wm = warp >> 1, wn = warp & 1;
    const int n0 = t * 1024 + nblk * 128;
    const int nb = t * 8 + nblk;

    int* pre = reinterpret_cast<int*>(smem + SMEM_PRE);
    int* srow = reinterpret_cast<int*>(smem + SMEM_SROW);

    reinterpret_cast<float*>(smem + SMEM_SC)[tid] = scales[n0 + tid];
    if (tid == 0) {
        int acc = 0;
#pragma unroll
        for (int p = 0; p < 8; p++) { pre[p] = acc; acc += g_cntp[t][p]; }
        pre[8] = acc;
#pragma unroll
        for (int s = 0; s < STAGES; s++) {
            mbar_init(sb + 8u * s, 1);        // full: TMA tx
            mbar_init(sb + 24u + 8u * s, 4);  // empty: 4 warp arrivals
        }
    }
    __syncthreads();

    const int cnt = pre[8];
    if (mblk * 128 >= cnt || cnt == 0) return;

    {   // srow for epilogue (row ids of this mblk's gathered rows)
        int gidx = mblk * 128 + tid;
        if (gidx >= cnt) gidx = cnt - 1;
        int p = 0;
#pragma unroll
        for (int q = 1; q < 8; q++) p += (gidx >= pre[q]) ? 1 : 0;
        srow[tid] = g_rows_part[t][p][gidx - pre[p]];
    }
    __syncthreads();

    const unsigned char* aSrc = g_At + (((size_t)(t * 32 + mblk)) << 20);
    const unsigned char* bSrc = g_Wt + ((size_t)nb << 20);

    auto fill = [&](int s, int kt) {
        uint32_t mb = sb + 8u * s;
        uint32_t st = sb + SMEM_ST + s * STAGE_BYTES;
        mbar_expect_tx(mb, STAGE_BYTES);
        bulk_g2s(st,         aSrc + ((size_t)kt << 14), 16384, mb);
        bulk_g2s(st + 16384, bSrc + ((size_t)kt << 14), 16384, mb);
    };
    const bool prod = (warp == 0) && elect_one();
    if (prod) {
#pragma unroll
        for (int s = 0; s < STAGES; s++) fill(s, s);
    }

    // ldmatrix addressing
    int aR[4], bR[4];
#pragma unroll
    for (int ms = 0; ms < 4; ms++) aR[ms] = wm * 64 + ms * 16 + (lane & 15);
    const int aCadd = lane >> 4;
#pragma unroll
    for (int nq = 0; nq < 4; nq++)
        bR[nq] = wn * 64 + nq * 16 + (lane & 7) + ((lane >> 4) << 3);
    const int bCadd = (lane >> 3) & 1;

    float d[4][8][4];
#pragma unroll
    for (int a = 0; a < 4; a++)
#pragma unroll
        for (int b = 0; b < 8; b++)
#pragma unroll
            for (int c = 0; c < 4; c++) d[a][b][c] = 0.f;

    for (int kt = 0; kt < NKT; kt++) {
        const int s = kt % 3;
        const uint32_t ph = (uint32_t)((kt / 3) & 1);
        mbar_wait(sb + 8u * s, ph);                       // data ready
        const uint32_t st = sb + SMEM_ST + s * STAGE_BYTES;
#pragma unroll
        for (int ks = 0; ks < 4; ks++) {
            uint32_t a[4][4], bf[4][4];
#pragma unroll
            for (int ms = 0; ms < 4; ms++) {
                uint32_t off = aR[ms] * 128 +
                               (((ks * 2 + aCadd) ^ (aR[ms] & 7)) << 4);
                ldm_x4(a[ms], st + off);
            }
#pragma unroll
            for (int nq = 0; nq < 4; nq++) {
                uint32_t off = bR[nq] * 128 +
                               (((ks * 2 + bCadd) ^ (bR[nq] & 7)) << 4);
                ldm_x4(bf[nq], st + 16384 + off);
            }
#pragma unroll
            for (int ms = 0; ms < 4; ms++)
#pragma unroll
                for (int nq = 0; nq < 4; nq++) {
                    hmma(d[ms][nq * 2],     a[ms], bf[nq][0], bf[nq][1]);
                    hmma(d[ms][nq * 2 + 1], a[ms], bf[nq][2], bf[nq][3]);
                }
        }
        if (elect_one()) mbar_arrive(sb + 24u + 8u * s);  // warp consumed
        if (prod && kt + STAGES < NKT) {
            mbar_wait(sb + 24u + 8u * s, ph);             // all 4 consumed
            fill(s, kt + STAGES);
        }
    }

    // epilogue: out = acc * scales[col] for gated rows (srow in smem)
    const float* sSc = reinterpret_cast<const float*>(smem + SMEM_SC);
#pragma unroll
    for (int ms = 0; ms < 4; ms++) {
#pragma unroll
        for (int half = 0; half < 2; half++) {
            int j = wm * 64 + ms * 16 + (lane >> 2) + half * 8;
            if (mblk * 128 + j >= cnt) continue;
            int row = srow[j];
            float* orow = out + (size_t)row * NDIM + n0;
#pragma unroll
            for (int ns = 0; ns < 8; ns++) {
                int col = wn * 64 + ns * 8 + (lane & 3) * 2;
                float2 v;
                v.x = d[ms][ns][half * 2]     * sSc[col];
                v.y = d[ms][ns][half * 2 + 1] * sSc[col + 1];
                *reinterpret_cast<float2*>(orow + col) = v;
            }
        }
    }
}

// ------------------------------ launch --------------------------------------

extern "C" void kernel_launch(void* const* d_in, const int* in_sizes, int n_in,
                              void* d_out, int out_size) {
    const float* x      = (const float*)d_in[0];
    const int*   gate   = (const int*)d_in[1];
    const float* weight = (const float*)d_in[2];
    const float* scales = (const float*)d_in[3];
    float* out = (float*)d_out;

    cudaFuncSetAttribute(trix_hmma,
                         cudaFuncAttributeMaxDynamicSharedMemorySize, SMEM_TOTAL);

    compact_parts<<<8, 256>>>(gate);
    prep_merged<<<PREP_BLKS, 256>>>(x, weight, gate, out);
    trix_hmma<<<dim3(8, 32, 4), 128, SMEM_TOTAL>>>(scales, out);
}

// round 17
// speedup vs baseline: 1.4216x; 1.0196x over previous
#include <cuda_runtime.h>
#include <cuda_fp16.h>
#include <cstdint>

// ---------------------------------------------------------------------------
// TriXLinear (sm_103 baseline PTX; tensor path = mma.sync m16n8k16 f16).
//   out = (x @ sign(W)^T) * scales * gate_mask
// x -> fp16 (norm rel err ~2.1e-4), W -> +-1 fp16 (exact). Gated-row GEMM.
// R17 = R13 + compact folded INTO prep_merged (blocks 0..7) with a
// release/acquire device flag; gather blocks spin until all 8 compact parts
// land (blocks 0..7 are wave-1-resident -> spin always terminates). GEMM
// CTA(0,0,0) resets the flag for graph replay. Everything else R13-exact.
// ---------------------------------------------------------------------------

#define MDIM 4096
#define NDIM 4096
#define KDIM 4096

#define NKT 64                          // K stages (64 fp16 = 128B rows)
#define STAGES 3
#define STAGE_BYTES 32768               // A 16K + B 16K
#define SMEM_SC   64                    // scales (512B)
#define SMEM_SROW 576                   // gathered row ids (512B)
#define SMEM_PRE  1088                  // part prefix (9 ints)
#define SMEM_ST   2048
#define SMEM_TOTAL (SMEM_ST + STAGES * STAGE_BYTES)   // 100352 -> 2 CTAs/SM
// mbarriers: full[s] at sb+8s, empty[s] at sb+24+8s  (s = 0..2)

// merged-prep partition (compact first: wave-1 residency guarantees progress)
#define COMPACT_BLKS 8
#define GATHER_BLKS  2048               // 32 mblk x 4 t x 16 kg
#define SIGNW_BLKS   8192
#define ZERO_BLKS    16384
#define PREP_BLKS (COMPACT_BLKS + GATHER_BLKS + SIGNW_BLKS + ZERO_BLKS)

// ------------------------------- scratch -----------------------------------
__device__ __align__(1024) unsigned char g_Wt[(size_t)32 * 1024 * 1024];
__device__ __align__(1024) unsigned char g_At[(size_t)128 * 1024 * 1024];
__device__ int g_cntp[4][8];            // per-tile per-part gated-row counts
__device__ int g_rows_part[4][8][512];  // per-part compacted row ids
__device__ int g_done;                  // compact completion counter (0 at load;
                                        // reset by GEMM for graph replays)

// ------------------------------ PTX helpers --------------------------------
__device__ __forceinline__ uint32_t smem_u32(const void* p) {
    uint32_t a;
    asm("{ .reg .u64 t; cvta.to.shared.u64 t, %1; cvt.u32.u64 %0, t; }"
        : "=r"(a) : "l"(p));
    return a;
}
__device__ __forceinline__ uint32_t elect_one() {
    uint32_t p;
    asm volatile("{ .reg .pred p; elect.sync _|p, 0xFFFFFFFF; selp.b32 %0,1,0,p; }"
                 : "=r"(p));
    return p;
}
__device__ __forceinline__ void mbar_init(uint32_t mb, uint32_t cnt) {
    asm volatile("mbarrier.init.shared.b64 [%0], %1;" :: "r"(mb), "r"(cnt) : "memory");
}
__device__ __forceinline__ void mbar_expect_tx(uint32_t mb, uint32_t bytes) {
    asm volatile("mbarrier.arrive.expect_tx.shared.b64 _, [%0], %1;"
                 :: "r"(mb), "r"(bytes) : "memory");
}
__device__ __forceinline__ void mbar_arrive(uint32_t mb) {
    asm volatile("mbarrier.arrive.shared.b64 _, [%0];" :: "r"(mb) : "memory");
}
__device__ __forceinline__ void mbar_wait(uint32_t mb, uint32_t parity) {
    asm volatile(
        "{\n\t.reg .pred P;\n\t"
        "WL_%=:\n\t"
        "mbarrier.try_wait.parity.acquire.cta.shared::cta.b64 P, [%0], %1, 0x989680;\n\t"
        "@P bra.uni WD_%=;\n\t"
        "bra.uni WL_%=;\n\t"
        "WD_%=:\n\t}"
        :: "r"(mb), "r"(parity) : "memory");
}
__device__ __forceinline__ void bulk_g2s(uint32_t dst, const void* src,
                                         uint32_t bytes, uint32_t mb) {
    asm volatile(
        "cp.async.bulk.shared::cta.global.mbarrier::complete_tx::bytes "
        "[%0], [%1], %2, [%3];"
        :: "r"(dst), "l"(src), "r"(bytes), "r"(mb) : "memory");
}
__device__ __forceinline__ void ldm_x4(uint32_t* r, uint32_t addr) {
    asm volatile("ldmatrix.sync.aligned.m8n8.x4.shared.b16 {%0,%1,%2,%3}, [%4];"
                 : "=r"(r[0]), "=r"(r[1]), "=r"(r[2]), "=r"(r[3]) : "r"(addr));
}
__device__ __forceinline__ void hmma(float* c, const uint32_t* a,
                                     uint32_t b0, uint32_t b1) {
    asm volatile(
        "mma.sync.aligned.m16n8k16.row.col.f32.f16.f16.f32 "
        "{%0,%1,%2,%3}, {%4,%5,%6,%7}, {%8,%9}, {%0,%1,%2,%3};"
        : "+f"(c[0]), "+f"(c[1]), "+f"(c[2]), "+f"(c[3])
        : "r"(a[0]), "r"(a[1]), "r"(a[2]), "r"(a[3]), "r"(b0), "r"(b1));
}

// ------------------------------ merged prep ---------------------------------
// blockIdx.x partition:
//   [0, 8)          compact part p (rows [p*512,(p+1)*512)) -> release g_done
//   [8, 2056)       gather+quant (acquire-spin on g_done == 8)
//   [2056, 10248)   sign_w -> fp16 swizzled tiles
//   [10248, ...)    zero ungated (row, tile) out blocks
__global__ __launch_bounds__(256) void prep_merged(
    const float* __restrict__ x,
    const float* __restrict__ w,
    const int* __restrict__ gate,
    float* __restrict__ out) {
    const int b = blockIdx.x;
    const int tid = threadIdx.x;

    if (b < COMPACT_BLKS) {
        // ---- compact part p (R13 compact_parts code, fenced release) ----
        const int p = b;
        __shared__ int scnt[4];
        if (tid < 4) scnt[tid] = 0;
        __syncthreads();
        int lane = tid & 31;
#pragma unroll
        for (int h = 0; h < 2; h++) {
            int r = p * 512 + h * 256 + tid;
#pragma unroll
            for (int t = 0; t < 4; t++) {
                bool pred = (gate[r * 4 + t] != 0);
                unsigned mask = __ballot_sync(0xFFFFFFFFu, pred);
                int cnt = __popc(mask);
                int base = 0;
                if (lane == 0 && cnt) base = atomicAdd(&scnt[t], cnt);
                base = __shfl_sync(0xFFFFFFFFu, base, 0);
                if (pred) {
                    int rank = __popc(mask & ((1u << lane) - 1u));
                    g_rows_part[t][p][base + rank] = r;
                }
            }
        }
        __syncthreads();
        if (tid < 4) g_cntp[tid][p] = scnt[tid];
        __syncthreads();
        if (tid == 0) {
            __threadfence();                      // release all part writes
            atomicAdd(&g_done, 1);
        }
    } else if (b < COMPACT_BLKS + GATHER_BLKS) {
        // ---- gather+quant: gated f32 x rows -> fp16 swizzled A tiles ----
        int gb = b - COMPACT_BLKS;
        int mblk = gb & 31, t = (gb >> 5) & 3, kg = gb >> 7;
        __shared__ int pre[9];
        __shared__ int srow[128];
        if (tid == 0) {
            int v;                                 // acquire-spin for compact
            do {
                asm volatile("ld.acquire.gpu.b32 %0, [%1];"
                             : "=r"(v) : "l"(&g_done));
            } while (v < COMPACT_BLKS);
            int acc = 0;
#pragma unroll
            for (int p = 0; p < 8; p++) { pre[p] = acc; acc += g_cntp[t][p]; }
            pre[8] = acc;
        }
        __syncthreads();
        const int cnt = pre[8];
        if (mblk * 128 >= cnt || cnt == 0) return;
        if (tid < 128) {
            int gidx = mblk * 128 + tid;
            if (gidx >= cnt) gidx = cnt - 1;
            int p = 0;
#pragma unroll
            for (int q = 1; q < 8; q++) p += (gidx >= pre[q]) ? 1 : 0;
            srow[tid] = g_rows_part[t][p][gidx - pre[p]];
        }
        __syncthreads();
        size_t base = ((size_t)(t * 32 + mblk)) << 20;
        int r = tid >> 3, c = tid & 7;        // 32 rows x 8 chunks / pass
#pragma unroll
        for (int kb = 0; kb < 4; kb++) {
            int kblk = kg * 4 + kb;
            size_t db = base + ((size_t)kblk << 14);
#pragma unroll
            for (int rp = 0; rp < 4; rp++) {
                int rr = r + rp * 32;
                const float4* src = reinterpret_cast<const float4*>(
                    x + (size_t)srow[rr] * KDIM + kblk * 64 + c * 8);
                float4 v0 = src[0], v1 = src[1];
                __half h[8];
                h[0] = __float2half_rn(v0.x); h[1] = __float2half_rn(v0.y);
                h[2] = __float2half_rn(v0.z); h[3] = __float2half_rn(v0.w);
                h[4] = __float2half_rn(v1.x); h[5] = __float2half_rn(v1.y);
                h[6] = __float2half_rn(v1.z); h[7] = __float2half_rn(v1.w);
                size_t dd = db + (size_t)rr * 128 + ((size_t)(c ^ (rr & 7)) << 4);
                *reinterpret_cast<uint4*>(g_At + dd) = *reinterpret_cast<uint4*>(h);
            }
        }
    } else if (b < COMPACT_BLKS + GATHER_BLKS + SIGNW_BLKS) {
        // ---- sign(W) -> fp16 swizzled tiles ----
        size_t idx = (size_t)(b - COMPACT_BLKS - GATHER_BLKS) * 256 + tid;
        int row = (int)(idx >> 9);
        int k0  = ((int)idx & 511) * 8;
        const float4* pp = reinterpret_cast<const float4*>(w + (size_t)row * KDIM + k0);
        float4 v0 = pp[0], v1 = pp[1];
        float f[8] = {v0.x, v0.y, v0.z, v0.w, v1.x, v1.y, v1.z, v1.w};
        __half s[8];
#pragma unroll
        for (int j = 0; j < 8; j++)
            s[j] = __float2half_rn((f[j] > 0.f) ? 1.f : ((f[j] < 0.f) ? -1.f : 0.f));
        int nb = row >> 7, r = row & 127, kblk = k0 >> 6;
        int c = (k0 & 63) >> 3;
        size_t off = (((size_t)(nb * 64 + kblk)) << 14) +
                     (size_t)r * 128 + ((size_t)(c ^ (r & 7)) << 4);
        *reinterpret_cast<uint4*>(g_Wt + off) = *reinterpret_cast<uint4*>(s);
    } else {
        // ---- zero ungated (row, tile) out blocks ----
        int bid = b - (COMPACT_BLKS + GATHER_BLKS + SIGNW_BLKS);   // 16384
        int r = bid >> 2, t = bid & 3;
        if (gate[r * 4 + t] != 0) return;
        float4 z = {0.f, 0.f, 0.f, 0.f};
        reinterpret_cast<float4*>(out + (size_t)r * NDIM + t * 1024)[tid] = z;
    }
}

// ------------------------------ GEMM kernel ---------------------------------
// grid (8 nblk, 32 mblk, 4 t), 128 threads, warp grid 2(M) x 2(N), warp 64x64.
// R13 mainloop; CTA(0,0,0) resets g_done for the next graph replay.

__global__ __launch_bounds__(128, 2) void trix_hmma(
    const float* __restrict__ scales,
    float* __restrict__ out) {
    const int t = blockIdx.z, mblk = blockIdx.y, nblk = blockIdx.x;

    // reset compact flag for next launch (stream-ordered after prep waits)
    if (nblk == 0 && mblk == 0 && t == 0 && threadIdx.x == 0) g_done = 0;

    extern __shared__ char smem[];
    const uint32_t sb = smem_u32(smem);
    const int tid = threadIdx.x;
    const int warp = tid >> 5, lane = tid & 31;
    const int wm = warp >> 1, wn = warp & 1;
    const int n0 = t * 1024 + nblk * 128;
    const int nb = t * 8 + nblk;

    int* pre = reinterpret_cast<int*>(smem + SMEM_PRE);
    int* srow = reinterpret_cast<int*>(smem + SMEM_SROW);

    reinterpret_cast<float*>(smem + SMEM_SC)[tid] = scales[n0 + tid];
    if (tid == 0) {
        int acc = 0;
#pragma unroll
        for (int p = 0; p < 8; p++) { pre[p] = acc; acc += g_cntp[t][p]; }
        pre[8] = acc;
#pragma unroll
        for (int s = 0; s < STAGES; s++) {
            mbar_init(sb + 8u * s, 1);        // full: TMA tx
            mbar_init(sb + 24u + 8u * s, 4);  // empty: 4 warp arrivals
        }
    }
    __syncthreads();

    const int cnt = pre[8];
    if (mblk * 128 >= cnt || cnt == 0) return;

    {   // srow for epilogue (row ids of this mblk's gathered rows)
        int gidx = mblk * 128 + tid;
        if (gidx >= cnt) gidx = cnt - 1;
        int p = 0;
#pragma unroll
        for (int q = 1; q < 8; q++) p += (gidx >= pre[q]) ? 1 : 0;
        srow[tid] = g_rows_part[t][p][gidx - pre[p]];
    }
    __syncthreads();

    const unsigned char* aSrc = g_At + (((size_t)(t * 32 + mblk)) << 20);
    const unsigned char* bSrc = g_Wt + ((size_t)nb << 20);

    auto fill = [&](int s, int kt) {
        uint32_t mb = sb + 8u * s;
        uint32_t st = sb + SMEM_ST + s * STAGE_BYTES;
        mbar_expect_tx(mb, STAGE_BYTES);
        bulk_g2s(st,         aSrc + ((size_t)kt << 14), 16384, mb);
        bulk_g2s(st + 16384, bSrc + ((size_t)kt << 14), 16384, mb);
    };
    const bool prod = (warp == 0) && elect_one();
    if (prod) {
#pragma unroll
        for (int s = 0; s < STAGES; s++) fill(s, s);
    }

    // ldmatrix addressing
    int aR[4], bR[4];
#pragma unroll
    for (int ms = 0; ms < 4; ms++) aR[ms] = wm * 64 + ms * 16 + (lane & 15);
    const int aCadd = lane >> 4;
#pragma unroll
    for (int nq = 0; nq < 4; nq++)
        bR[nq] = wn * 64 + nq * 16 + (lane & 7) + ((lane >> 4) << 3);
    const int bCadd = (lane >> 3) & 1;

    float d[4][8][4];
#pragma unroll
    for (int a = 0; a < 4; a++)
#pragma unroll
        for (int b = 0; b < 8; b++)
#pragma unroll
            for (int c = 0; c < 4; c++) d[a][b][c] = 0.f;

    for (int kt = 0; kt < NKT; kt++) {
        const int s = kt % 3;
        const uint32_t ph = (uint32_t)((kt / 3) & 1);
        mbar_wait(sb + 8u * s, ph);                       // data ready
        const uint32_t st = sb + SMEM_ST + s * STAGE_BYTES;
#pragma unroll
        for (int ks = 0; ks < 4; ks++) {
            uint32_t a[4][4], bf[4][4];
#pragma unroll
            for (int ms = 0; ms < 4; ms++) {
                uint32_t off = aR[ms] * 128 +
                               (((ks * 2 + aCadd) ^ (aR[ms] & 7)) << 4);
                ldm_x4(a[ms], st + off);
            }
#pragma unroll
            for (int nq = 0; nq < 4; nq++) {
                uint32_t off = bR[nq] * 128 +
                               (((ks * 2 + bCadd) ^ (bR[nq] & 7)) << 4);
                ldm_x4(bf[nq], st + 16384 + off);
            }
#pragma unroll
            for (int ms = 0; ms < 4; ms++)
#pragma unroll
                for (int nq = 0; nq < 4; nq++) {
                    hmma(d[ms][nq * 2],     a[ms], bf[nq][0], bf[nq][1]);
                    hmma(d[ms][nq * 2 + 1], a[ms], bf[nq][2], bf[nq][3]);
                }
        }
        if (elect_one()) mbar_arrive(sb + 24u + 8u * s);  // warp consumed
        if (prod && kt + STAGES < NKT) {
            mbar_wait(sb + 24u + 8u * s, ph);             // all 4 consumed
            fill(s, kt + STAGES);
        }
    }

    // epilogue: out = acc * scales[col] for gated rows (srow in smem)
    const float* sSc = reinterpret_cast<const float*>(smem + SMEM_SC);
#pragma unroll
    for (int ms = 0; ms < 4; ms++) {
#pragma unroll
        for (int half = 0; half < 2; half++) {
            int j = wm * 64 + ms * 16 + (lane >> 2) + half * 8;
            if (mblk * 128 + j >= cnt) continue;
            int row = srow[j];
            float* orow = out + (size_t)row * NDIM + n0;
#pragma unroll
            for (int ns = 0; ns < 8; ns++) {
                int col = wn * 64 + ns * 8 + (lane & 3) * 2;
                float2 v;
                v.x = d[ms][ns][half * 2]     * sSc[col];
                v.y = d[ms][ns][half * 2 + 1] * sSc[col + 1];
                *reinterpret_cast<float2*>(orow + col) = v;
            }
        }
    }
}

// ------------------------------ launch --------------------------------------

extern "C" void kernel_launch(void* const* d_in, const int* in_sizes, int n_in,
                              void* d_out, int out_size) {
    const float* x      = (const float*)d_in[0];
    const int*   gate   = (const int*)d_in[1];
    const float* weight = (const float*)d_in[2];
    const float* scales = (const float*)d_in[3];
    float* out = (float*)d_out;

    cudaFuncSetAttribute(trix_hmma,
                         cudaFuncAttributeMaxDynamicSharedMemorySize, SMEM_TOTAL);

    prep_merged<<<PREP_BLKS, 256>>>(x, weight, gate, out);
    trix_hmma<<<dim3(8, 32, 4), 128, SMEM_TOTAL>>>(scales, out);
}